// round 9
// baseline (speedup 1.0000x reference)
#include <cuda_runtime.h>
#include <cstddef>

// Problem constants (from reference)
#define BB       16     // batch
#define SS       256    // SU == SV
#define DEG      3      // P == Q
#define KLEN     132    // M + P + 2 == N + Q + 2
#define NCTRL    128    // M + 1 == N + 1
#define MAXSPAN  127    // M == N
#define NINNER   (KLEN - 2 * DEG)   // 126
#define EPSF     1e-8f
#define ROWS     4      // u-rows per eval block

// Scratch: basis weights and spans for both axes. axis 0 = u, axis 1 = v.
__device__ float g_N[2][BB][DEG + 1][SS];
__device__ int   g_span[2][BB][SS];

// ---------------------------------------------------------------------------
// Kernel 1: knot normalization + span search + Cox-de Boor basis.
// Grid: (BB, 2)  Block: SS threads. One block handles one (batch, axis).
// ---------------------------------------------------------------------------
__global__ void basis_kernel(const float* __restrict__ knot_u,
                             const float* __restrict__ knot_v,
                             const float* __restrict__ uu,
                             const float* __restrict__ vv)
{
    __shared__ float Ksh[KLEN];
    const int b    = blockIdx.x;
    const int axis = blockIdx.y;
    const int tid  = threadIdx.x;

    const float* kn = (axis == 0 ? knot_u : knot_v) + b * KLEN;

    // load raw knots, clamp negatives (reference: where(knots<0, 1e-4, knots))
    if (tid < KLEN) {
        float x = kn[tid];
        Ksh[tid] = (x < 0.0f) ? 1e-4f : x;
    }
    __syncthreads();

    // serial inclusive cumsum (matches jnp.cumsum order)
    if (tid == 0) {
        float acc = 0.0f;
        for (int i = 0; i < KLEN; i++) { acc += Ksh[i]; Ksh[i] = acc; }
    }
    __syncthreads();

    // normalize: (kc - kc[0]) / (kc[-1] - kc[0])
    const float k0  = Ksh[0];
    const float den = Ksh[KLEN - 1] - Ksh[0];
    __syncthreads();
    if (tid < KLEN) Ksh[tid] = (Ksh[tid] - k0) / den;
    __syncthreads();

    // one sample per thread
    const float t = (axis == 0 ? uu : vv)[tid];

    // span: literal replication of argmin(where(d > EPS, d, 1.0)), first-min
    float best = 3.4e38f;
    int   bi   = 0;
    for (int i = 0; i < NINNER; i++) {
        float d = t - Ksh[DEG + i];
        float m = (d > EPSF) ? d : 1.0f;
        if (m < best) { best = m; bi = i; }
    }
    int span = bi + DEG;
    if (span > MAXSPAN) span = MAXSPAN;
    if (span < DEG)     span = DEG;

    // Cox-de Boor basis, degree 3 (exact fp order of the reference)
    float Nf[DEG + 1];
    Nf[0] = 1.0f; Nf[1] = 0.0f; Nf[2] = 0.0f; Nf[3] = 0.0f;
    #pragma unroll
    for (int k = 1; k <= DEG; k++) {
        float saved = 0.0f;
        #pragma unroll
        for (int r = 0; r < k; r++) {
            float K1 = Ksh[span + r + 1];
            float K2 = Ksh[span + 1 - k + r];
            float denom = (K1 - t) + (t - K2);
            float temp  = (denom == 0.0f) ? 1e-4f : (Nf[r] / denom);
            Nf[r] = saved + (K1 - t) * temp;
            saved = (t - K2) * temp;
        }
        Nf[k] = saved;
    }

    g_span[axis][b][tid] = span;
    #pragma unroll
    for (int k = 0; k <= DEG; k++)
        g_N[axis][b][k][tid] = Nf[k];
}

// ---------------------------------------------------------------------------
// Kernel 2: surface evaluation, ROWS u-rows per block.
// Grid: (SS/ROWS, BB)  Block: SS threads (one per v sample).
//
// Phase A: blend ROWS x (4 ctrl rows) into ROWS shared rows of 384 floats
//          (float4-coalesced; ctrl is L2-resident). 384 float4 outputs,
//          1.5 per thread.
// Phase B: each thread does the 4-tap v reduction for its v across all
//          ROWS rows (v-weights loaded ONCE, reused ROWS times).
// Phase C: float4-coalesced stores, 3 per thread.
// Only 2 barriers per block.
// ---------------------------------------------------------------------------
__global__ void eval_kernel(const float* __restrict__ ctrl,
                            float* __restrict__ out)
{
    __shared__ float srow[ROWS][NCTRL * 3];   // blended control rows
    __shared__ float sout[ROWS][SS * 3];      // output staging

    const int b   = blockIdx.y;
    const int iu0 = blockIdx.x * ROWS;
    const int tid = threadIdx.x;

    // ---- Phase A: blend. 4*96 = 384 float4 outputs over 256 threads.
    #pragma unroll
    for (int i = tid; i < ROWS * (NCTRL * 3) / 4; i += SS) {
        const int r  = i / ((NCTRL * 3) / 4);
        const int j  = i % ((NCTRL * 3) / 4);
        const int iu = iu0 + r;

        const int   su = g_span[0][b][iu];
        const float w0 = g_N[0][b][0][iu];
        const float w1 = g_N[0][b][1][iu];
        const float w2 = g_N[0][b][2][iu];
        const float w3 = g_N[0][b][3][iu];

        const float4* c0 =
            (const float4*)(ctrl + ((size_t)b * NCTRL + (size_t)(su - DEG)) * (NCTRL * 3));

        float4 a = c0[j];
        float4 p = c0[j +     (NCTRL * 3) / 4];
        float4 q = c0[j + 2 * (NCTRL * 3) / 4];
        float4 rr= c0[j + 3 * (NCTRL * 3) / 4];
        float4 s;
        s.x = w0 * a.x + w1 * p.x + w2 * q.x + w3 * rr.x;
        s.y = w0 * a.y + w1 * p.y + w2 * q.y + w3 * rr.y;
        s.z = w0 * a.z + w1 * p.z + w2 * q.z + w3 * rr.z;
        s.w = w0 * a.w + w1 * p.w + w2 * q.w + w3 * rr.w;
        ((float4*)srow[r])[j] = s;
    }
    __syncthreads();

    // ---- Phase B: v reduction. v-weights loaded once, reused ROWS times.
    {
        const int   sv = g_span[1][b][tid];
        const float q0 = g_N[1][b][0][tid];
        const float q1 = g_N[1][b][1][tid];
        const float q2 = g_N[1][b][2][tid];
        const float q3 = g_N[1][b][3][tid];
        const int   o  = (sv - DEG) * 3;

        #pragma unroll
        for (int r = 0; r < ROWS; r++) {
            #pragma unroll
            for (int d = 0; d < 3; d++) {
                sout[r][tid * 3 + d] = q0 * srow[r][o + d]
                                     + q1 * srow[r][o + 3 + d]
                                     + q2 * srow[r][o + 6 + d]
                                     + q3 * srow[r][o + 9 + d];
            }
        }
    }
    __syncthreads();

    // ---- Phase C: stores. ROWS*192 = 768 float4 over 256 threads (3 each).
    float4* ob = (float4*)(out + ((size_t)b * SS + (size_t)iu0) * (SS * 3));
    const float4* sb = (const float4*)&sout[0][0];
    #pragma unroll
    for (int i = tid; i < ROWS * (SS * 3) / 4; i += SS)
        ob[i] = sb[i];   // sout rows are contiguous; out rows are contiguous
}

// ---------------------------------------------------------------------------
// Launch. Inputs (metadata order): ctrl_pts, knot_u, knot_v, u, v
// ---------------------------------------------------------------------------
extern "C" void kernel_launch(void* const* d_in, const int* in_sizes, int n_in,
                              void* d_out, int out_size)
{
    const float* ctrl = (const float*)d_in[0];   // (16,128,128,3)
    const float* ku   = (const float*)d_in[1];   // (16,132)
    const float* kv   = (const float*)d_in[2];   // (16,132)
    const float* u    = (const float*)d_in[3];   // (256,)
    const float* v    = (const float*)d_in[4];   // (256,)
    float*       out  = (float*)d_out;           // (16,256,256,3)

    basis_kernel<<<dim3(BB, 2), SS>>>(ku, kv, u, v);
    eval_kernel<<<dim3(SS / ROWS, BB), SS>>>(ctrl, out);
}